// round 12
// baseline (speedup 1.0000x reference)
#include <cuda_runtime.h>
#include <cuda_bf16.h>
#include <math.h>
#include <stdint.h>

#define N_NODES 50000
#define N_EDGES 800000
#define DIM     256
#define DEPTH   4
#define N_REL   4
#define LN_EPS  1e-5f
#define NCOL    1280          // 4 relations * 256 + root 256

#define EPB 1024                              // edges per partition block
#define NPB ((N_EDGES + EPB - 1) / EPB)       // 782

typedef __nv_bfloat16 bf16;

// ---------------------------------------------------------------------------
// Scratch (device globals: allocation-free per harness rules)
// ---------------------------------------------------------------------------
__device__ float g_H[(size_t)N_NODES * (N_REL * DIM)];   // per-relation transforms [N,1024]
__device__ float g_OUT[(size_t)N_NODES * DIM];           // agg + X@root + bias
__device__ float g_bufA[(size_t)N_NODES * DIM];          // X ping
__device__ float g_bufB[(size_t)N_NODES * DIM];          // X pong
__device__ bf16  g_Xhi[(size_t)N_NODES * DIM];           // bf16 hi split of X
__device__ bf16  g_Xlo[(size_t)N_NODES * DIM];           // bf16 lo split of X
__device__ bf16  g_Bhi[(size_t)DEPTH * NCOL * DIM];      // W^T hi  [l][n][k]
__device__ bf16  g_Blo[(size_t)DEPTH * NCOL * DIM];      // W^T lo
__device__ int   g_cnt[N_NODES * N_REL];

// edge partition (type-major ordering)
__device__ int   g_blkcnt[N_REL * NPB];
__device__ int   g_blkoff[N_REL * NPB];
__device__ int   g_pgat[N_EDGES];    // src*4 + type  (row in H viewed as [4N,256])
__device__ int   g_pdst[N_EDGES];
__device__ float g_pinv[N_EDGES];

// ---------------------------------------------------------------------------
// PTX helpers (plain sm_80-era instructions -> assemble at target sm_103)
// ---------------------------------------------------------------------------
__device__ __forceinline__ uint32_t smem_u32(const void* p) {
    uint32_t a;
    asm("{ .reg .u64 t; cvta.to.shared.u64 t, %1; cvt.u32.u64 %0, t; }"
        : "=r"(a) : "l"(p));
    return a;
}

__device__ __forceinline__ void ldsm_x4(uint32_t& r0, uint32_t& r1,
                                        uint32_t& r2, uint32_t& r3, uint32_t addr) {
    asm volatile("ldmatrix.sync.aligned.m8n8.x4.shared.b16 {%0,%1,%2,%3}, [%4];"
                 : "=r"(r0), "=r"(r1), "=r"(r2), "=r"(r3) : "r"(addr));
}

#define MMA_BF16(c, a, b0v, b1v)                                             \
    asm volatile(                                                            \
        "mma.sync.aligned.m16n8k16.row.col.f32.bf16.bf16.f32 "               \
        "{%0,%1,%2,%3}, {%4,%5,%6,%7}, {%8,%9}, {%0,%1,%2,%3};"              \
        : "+f"((c)[0]), "+f"((c)[1]), "+f"((c)[2]), "+f"((c)[3])             \
        : "r"((a)[0]), "r"((a)[1]), "r"((a)[2]), "r"((a)[3]),                \
          "r"(b0v), "r"(b1v))

#define CPA16(dst, src)                                                      \
    asm volatile("cp.async.cg.shared.global [%0], [%1], 16;"                 \
                 :: "r"(dst), "l"(src) : "memory")
#define CPA_COMMIT() asm volatile("cp.async.commit_group;" ::: "memory")
#define CPA_WAIT(n)  asm volatile("cp.async.wait_group %0;" :: "n"(n) : "memory")

#define SW(o) ((uint32_t)(o) ^ ((((uint32_t)(o)) >> 3) & 0x70))

// ---------------------------------------------------------------------------
// Setup kernels (once per launch)
// ---------------------------------------------------------------------------
__global__ void zero_cnt_kernel() {
    int i = blockIdx.x * blockDim.x + threadIdx.x;
    if (i < N_NODES * N_REL) g_cnt[i] = 0;
}

__global__ void count_kernel(const int* __restrict__ dst, const int* __restrict__ et) {
    int e = blockIdx.x * blockDim.x + threadIdx.x;
    if (e < N_EDGES) atomicAdd(&g_cnt[dst[e] * N_REL + et[e]], 1);
}

// per-block type histogram
__global__ void hist_kernel(const int* __restrict__ et) {
    __shared__ int sc[N_REL];
    int b = blockIdx.x;
    if (threadIdx.x < N_REL) sc[threadIdx.x] = 0;
    __syncthreads();
    #pragma unroll
    for (int i = 0; i < EPB / 256; i++) {
        int e = b * EPB + threadIdx.x + i * 256;
        if (e < N_EDGES) atomicAdd(&sc[et[e]], 1);
    }
    __syncthreads();
    if (threadIdx.x < N_REL) g_blkcnt[threadIdx.x * NPB + b] = sc[threadIdx.x];
}

// tiny sequential scan (one block)
__global__ void scan_kernel() {
    __shared__ int base[N_REL + 1];
    if (threadIdx.x == 0) {
        int acc = 0;
        base[0] = 0;
        for (int t = 0; t < N_REL; t++) {
            int s = 0;
            for (int b = 0; b < NPB; b++) s += g_blkcnt[t * NPB + b];
            acc += s;
            base[t + 1] = acc;
        }
    }
    __syncthreads();
    int t = threadIdx.x;
    if (t < N_REL) {
        int run = base[t];
        for (int b = 0; b < NPB; b++) {
            g_blkoff[t * NPB + b] = run;
            run += g_blkcnt[t * NPB + b];
        }
    }
}

// scatter edges into type-major order with fused gather index + inv_deg
__global__ void scatter_kernel(const int* __restrict__ src,
                               const int* __restrict__ dst,
                               const int* __restrict__ et) {
    __shared__ int soff[N_REL];
    int b = blockIdx.x;
    if (threadIdx.x < N_REL) soff[threadIdx.x] = g_blkoff[threadIdx.x * NPB + b];
    __syncthreads();
    #pragma unroll
    for (int i = 0; i < EPB / 256; i++) {
        int e = b * EPB + threadIdx.x + i * 256;
        if (e < N_EDGES) {
            int t = et[e];
            int pos = atomicAdd(&soff[t], 1);
            int d = dst[e];
            int c = g_cnt[d * N_REL + t];
            g_pgat[pos] = src[e] * N_REL + t;
            g_pdst[pos] = d;
            g_pinv[pos] = 1.0f / (float)(c > 1 ? c : 1);
        }
    }
}

__device__ __forceinline__ void bf16_split(float x, bf16& h, bf16& l) {
    h = __float2bfloat16(x);
    l = __float2bfloat16(x - __bfloat162float(h));
}

// split node embedding into bf16 hi/lo
__global__ void xsplit_kernel(const float* __restrict__ X,
                              bf16* __restrict__ hi, bf16* __restrict__ lo) {
    int i = blockIdx.x * 256 + threadIdx.x;
    bf16 h, l;
    bf16_split(X[i], h, l);
    hi[i] = h; lo[i] = l;
}

// transpose + split weights: Bhi/Blo[l][n][k] = split(W[l][rel][k][n] or root[l][k][n])
__global__ void wsplit_kernel(const float* __restrict__ W, const float* __restrict__ R,
                              bf16* __restrict__ Bhi, bf16* __restrict__ Blo) {
    __shared__ float t[32][33];
    int l  = blockIdx.z;
    int n0 = blockIdx.x * 32;
    int k0 = blockIdx.y * 32;
    int tx = threadIdx.x, ty = threadIdx.y;   // 32 x 8
    int rel = n0 >> 8;

    #pragma unroll
    for (int j = 0; j < 4; j++) {
        int k = k0 + ty + j * 8;
        float v;
        if (rel < 4)
            v = W[(((size_t)l * 4 + rel) * 256 + k) * 256 + (n0 & 255) + tx];
        else
            v = R[((size_t)l * 256 + k) * 256 + (n0 - 1024) + tx];
        t[ty + j * 8][tx] = v;
    }
    __syncthreads();
    #pragma unroll
    for (int j = 0; j < 4; j++) {
        int n = ty + j * 8;
        float x = t[tx][n];                    // = src[k0+tx][n0+n]
        bf16 h, lo;
        bf16_split(x, h, lo);
        size_t o = ((size_t)l * NCOL + n0 + n) * 256 + k0 + tx;
        Bhi[o] = h;
        Blo[o] = lo;
    }
}

// ---------------------------------------------------------------------------
// bf16 3-product GEMM via mma.sync: C[50000,1280] = X @ Wcat^T
//   C = Xhi*Bhi + Xlo*Bhi + Xhi*Blo  (fp32 accumulate)
// CTA tile 128x128, 8 warps (64x32 each), K chunks of 32 (hi|lo packed in
// one 128B SW128 row), 2-stage cp.async pipeline.
//   col tiles 0..7 -> g_H [N,1024];  col tiles 8..9 -> g_OUT (+bias)
// ---------------------------------------------------------------------------
#define STAGE_BYTES 32768          // A tile 16KB + B tile 16KB
#define SMEM_BYTES  (2 * STAGE_BYTES)

__device__ __forceinline__ void issue_stage(
    uint32_t smBase, int buf, int kc, int row0, int n0, int tid,
    const bf16* __restrict__ Xhi, const bf16* __restrict__ Xlo,
    const bf16* __restrict__ Bhi, const bf16* __restrict__ Blo)
{
    uint32_t aB = smBase + buf * STAGE_BYTES;
    uint32_t bB = aB + 16384;
    #pragma unroll
    for (int t = 0; t < 4; t++) {
        int j   = tid + t * 256;
        int row = j >> 3, ch = j & 7;
        int gr  = row0 + row;
        if (gr > N_NODES - 1) gr = N_NODES - 1;      // clamp; stores are guarded
        const bf16* src = (ch < 4 ? Xhi : Xlo) + (size_t)gr * 256 + kc * 32 + (ch & 3) * 8;
        CPA16(aB + SW(row * 128 + ch * 16), src);
    }
    #pragma unroll
    for (int t = 0; t < 4; t++) {
        int j   = tid + t * 256;
        int row = j >> 3, ch = j & 7;
        const bf16* src = (ch < 4 ? Bhi : Blo) + (size_t)(n0 + row) * 256 + kc * 32 + (ch & 3) * 8;
        CPA16(bB + SW(row * 128 + ch * 16), src);
    }
}

__global__ __launch_bounds__(256) void gemm_tc(
    const bf16* __restrict__ Xhi, const bf16* __restrict__ Xlo,
    const bf16* __restrict__ Bhi, const bf16* __restrict__ Blo,
    const float* __restrict__ bias,
    float* __restrict__ H, float* __restrict__ OUT)
{
    extern __shared__ __align__(1024) char sm[];
    const uint32_t smBase = smem_u32(sm);
    const int tid  = threadIdx.x;
    const int wid  = tid >> 5;
    const int lane = tid & 31;
    const int wm   = wid >> 2;          // 0..1  (64-row slab)
    const int wn   = wid & 3;           // 0..3  (32-col slab)
    const int n0   = blockIdx.x * 128;
    const int row0 = blockIdx.y * 128;

    float acc[4][4][4];
    #pragma unroll
    for (int i = 0; i < 4; i++)
        #pragma unroll
        for (int j = 0; j < 4; j++)
            #pragma unroll
            for (int k = 0; k < 4; k++) acc[i][j][k] = 0.f;

    const int lr  = lane & 7;
    const int ls1 = (lane >> 3) & 1;
    const int ls2 = lane >> 4;

    issue_stage(smBase, 0, 0, row0, n0, tid, Xhi, Xlo, Bhi, Blo);
    CPA_COMMIT();

    int buf = 0;
    for (int kc = 0; kc < 8; kc++) {
        if (kc < 7) {
            issue_stage(smBase, buf ^ 1, kc + 1, row0, n0, tid, Xhi, Xlo, Bhi, Blo);
            CPA_COMMIT();
            CPA_WAIT(1);
        } else {
            CPA_WAIT(0);
        }
        __syncthreads();

        uint32_t aB = smBase + buf * STAGE_BYTES;
        uint32_t bB = aB + 16384;

        #pragma unroll
        for (int kk = 0; kk < 2; kk++) {
            const int ch_hi = 2 * kk;        // 16B chunks 0..3 = hi, 4..7 = lo
            const int ch_lo = 4 + 2 * kk;

            uint32_t ahi[4][4], alo[4][4], bhi[2][4], blo[2][4];

            #pragma unroll
            for (int mf = 0; mf < 4; mf++) {
                int mrow = wm * 64 + mf * 16 + ls1 * 8 + lr;
                int ch   = ch_hi + ls2;
                ldsm_x4(ahi[mf][0], ahi[mf][1], ahi[mf][2], ahi[mf][3],
                        aB + SW(mrow * 128 + ch * 16));
            }
            #pragma unroll
            for (int np = 0; np < 2; np++) {
                int nrow = wn * 32 + np * 16 + ls2 * 8 + lr;
                int ch   = ch_hi + ls1;
                ldsm_x4(bhi[np][0], bhi[np][1], bhi[np][2], bhi[np][3],
                        bB + SW(nrow * 128 + ch * 16));
            }
            #pragma unroll
            for (int mf = 0; mf < 4; mf++)
                #pragma unroll
                for (int nf = 0; nf < 4; nf++)
                    MMA_BF16(acc[mf][nf], ahi[mf],
                             bhi[nf >> 1][(nf & 1) * 2], bhi[nf >> 1][(nf & 1) * 2 + 1]);

            #pragma unroll
            for (int mf = 0; mf < 4; mf++) {
                int mrow = wm * 64 + mf * 16 + ls1 * 8 + lr;
                int ch   = ch_lo + ls2;
                ldsm_x4(alo[mf][0], alo[mf][1], alo[mf][2], alo[mf][3],
                        aB + SW(mrow * 128 + ch * 16));
            }
            #pragma unroll
            for (int mf = 0; mf < 4; mf++)
                #pragma unroll
                for (int nf = 0; nf < 4; nf++)
                    MMA_BF16(acc[mf][nf], alo[mf],
                             bhi[nf >> 1][(nf & 1) * 2], bhi[nf >> 1][(nf & 1) * 2 + 1]);

            #pragma unroll
            for (int np = 0; np < 2; np++) {
                int nrow = wn * 32 + np * 16 + ls2 * 8 + lr;
                int ch   = ch_lo + ls1;
                ldsm_x4(blo[np][0], blo[np][1], blo[np][2], blo[np][3],
                        bB + SW(nrow * 128 + ch * 16));
            }
            #pragma unroll
            for (int mf = 0; mf < 4; mf++)
                #pragma unroll
                for (int nf = 0; nf < 4; nf++)
                    MMA_BF16(acc[mf][nf], ahi[mf],
                             blo[nf >> 1][(nf & 1) * 2], blo[nf >> 1][(nf & 1) * 2 + 1]);
        }
        __syncthreads();
        buf ^= 1;
    }

    // ---- epilogue: direct fp32 stores ----
    const int g  = lane >> 2;
    const int tg = lane & 3;
    const bool isroot = (n0 >= 1024);

    #pragma unroll
    for (int nf = 0; nf < 4; nf++) {
        int col = n0 + wn * 32 + nf * 8 + tg * 2;
        float b0 = 0.f, b1 = 0.f;
        if (isroot) { b0 = bias[col - 1024]; b1 = bias[col - 1023]; }
        #pragma unroll
        for (int mf = 0; mf < 4; mf++) {
            int r0 = row0 + wm * 64 + mf * 16 + g;
            int r1 = r0 + 8;
            float2 v0 = make_float2(acc[mf][nf][0] + b0, acc[mf][nf][1] + b1);
            float2 v1 = make_float2(acc[mf][nf][2] + b0, acc[mf][nf][3] + b1);
            if (isroot) {
                if (r0 < N_NODES) *(float2*)(OUT + (size_t)r0 * 256 + col - 1024) = v0;
                if (r1 < N_NODES) *(float2*)(OUT + (size_t)r1 * 256 + col - 1024) = v1;
            } else {
                if (r0 < N_NODES) *(float2*)(H + (size_t)r0 * 1024 + col) = v0;
                if (r1 < N_NODES) *(float2*)(H + (size_t)r1 * 1024 + col) = v1;
            }
        }
    }
}

// ---------------------------------------------------------------------------
// Edge aggregation (type-major partitioned): OUT[dst] += inv * H[gat]
// Gather source per type is 51MB -> L2 resident.
// ---------------------------------------------------------------------------
__global__ void edge_kernel(const float* __restrict__ H,
                            float* __restrict__ OUT)
{
    int e    = blockIdx.x * 4 + (threadIdx.x >> 6);
    int lane = threadIdx.x & 63;

    int   g   = g_pgat[e];
    int   d   = g_pdst[e];
    float inv = g_pinv[e];

    float4 v = *(const float4*)(H + (size_t)g * DIM + lane * 4);
    v.x *= inv; v.y *= inv; v.z *= inv; v.w *= inv;

    float* p = OUT + (size_t)d * DIM + lane * 4;
    asm volatile("red.global.add.v4.f32 [%0], {%1, %2, %3, %4};"
                 :: "l"(p), "f"(v.x), "f"(v.y), "f"(v.z), "f"(v.w)
                 : "memory");
}

// ---------------------------------------------------------------------------
// LayerNorm + ELU + residual (warp per row, 8 floats/lane), fused bf16 split
// ---------------------------------------------------------------------------
__global__ __launch_bounds__(256) void ln_kernel(
        const float* __restrict__ OUT,
        const float* __restrict__ Xin,
        const float* __restrict__ gamma,
        const float* __restrict__ beta,
        float* __restrict__ Xout,
        bf16* __restrict__ Xhi,
        bf16* __restrict__ Xlo)
{
    int row  = blockIdx.x * 8 + (threadIdx.x >> 5);
    int lane = threadIdx.x & 31;
    size_t base = (size_t)row * DIM + lane * 8;

    float v[8];
    *(float4*)&v[0] = *(const float4*)(OUT + base);
    *(float4*)&v[4] = *(const float4*)(OUT + base + 4);

    float s = v[0] + v[1] + v[2] + v[3] + v[4] + v[5] + v[6] + v[7];
    #pragma unroll
    for (int o = 16; o > 0; o >>= 1) s += __shfl_xor_sync(0xffffffffu, s, o);
    float mu = s * (1.0f / DIM);

    float q = 0.f;
    #pragma unroll
    for (int k = 0; k < 8; k++) { float dl = v[k] - mu; q += dl * dl; }
    #pragma unroll
    for (int o = 16; o > 0; o >>= 1) q += __shfl_xor_sync(0xffffffffu, q, o);
    float rstd = rsqrtf(q * (1.0f / DIM) + LN_EPS);

    float gmv[8], btv[8], xi[8];
    *(float4*)&gmv[0] = *(const float4*)(gamma + lane * 8);
    *(float4*)&gmv[4] = *(const float4*)(gamma + lane * 8 + 4);
    *(float4*)&btv[0] = *(const float4*)(beta + lane * 8);
    *(float4*)&btv[4] = *(const float4*)(beta + lane * 8 + 4);
    *(float4*)&xi[0]  = *(const float4*)(Xin + base);
    *(float4*)&xi[4]  = *(const float4*)(Xin + base + 4);

    float r[8];
    ushort hi[8], lo[8];
    #pragma unroll
    for (int k = 0; k < 8; k++) {
        float y = (v[k] - mu) * rstd * gmv[k] + btv[k];
        y = (y > 0.f) ? y : expm1f(y);
        r[k] = y + xi[k];
        bf16 h, l;
        bf16_split(r[k], h, l);
        hi[k] = __bfloat16_as_ushort(h);
        lo[k] = __bfloat16_as_ushort(l);
    }

    *(float4*)(Xout + base)     = *(float4*)&r[0];
    *(float4*)(Xout + base + 4) = *(float4*)&r[4];
    *(uint4*)(Xhi + base) = *(uint4*)&hi[0];
    *(uint4*)(Xlo + base) = *(uint4*)&lo[0];
}

// ---------------------------------------------------------------------------
// Driver
// ---------------------------------------------------------------------------
extern "C" void kernel_launch(void* const* d_in, const int* in_sizes, int n_in,
                              void* d_out, int out_size)
{
    const float* node    = (const float*)d_in[0];
    const float* weights = (const float*)d_in[1];   // [4,4,256,256]
    const float* roots   = (const float*)d_in[2];   // [4,256,256]
    const float* biases  = (const float*)d_in[3];   // [4,256]
    const float* gamma   = (const float*)d_in[4];   // [4,256]
    const float* beta    = (const float*)d_in[5];   // [4,256]
    const int*   eidx    = (const int*)d_in[6];     // [2,800000]
    const int*   etype   = (const int*)d_in[7];     // [800000]
    const int*   srcv    = eidx;
    const int*   dstv    = eidx + N_EDGES;
    float*       out     = (float*)d_out;

    float *H, *OUTb, *bufA, *bufB;
    bf16 *Xhi, *Xlo, *Bhi, *Blo;
    cudaGetSymbolAddress((void**)&H,    g_H);
    cudaGetSymbolAddress((void**)&OUTb, g_OUT);
    cudaGetSymbolAddress((void**)&bufA, g_bufA);
    cudaGetSymbolAddress((void**)&bufB, g_bufB);
    cudaGetSymbolAddress((void**)&Xhi,  g_Xhi);
    cudaGetSymbolAddress((void**)&Xlo,  g_Xlo);
    cudaGetSymbolAddress((void**)&Bhi,  g_Bhi);
    cudaGetSymbolAddress((void**)&Blo,  g_Blo);

    static int smem_set = 0;
    if (!smem_set) {
        cudaFuncSetAttribute(gemm_tc, cudaFuncAttributeMaxDynamicSharedMemorySize, SMEM_BYTES);
        smem_set = 1;
    }

    // once per launch: degree histogram, edge partition, operand splits
    zero_cnt_kernel<<<(N_NODES * N_REL + 255) / 256, 256>>>();
    count_kernel<<<(N_EDGES + 255) / 256, 256>>>(dstv, etype);
    hist_kernel<<<NPB, 256>>>(etype);
    scan_kernel<<<1, 32>>>();
    scatter_kernel<<<NPB, 256>>>(srcv, dstv, etype);
    wsplit_kernel<<<dim3(NCOL / 32, DIM / 32, DEPTH), dim3(32, 8)>>>(weights, roots, Bhi, Blo);
    xsplit_kernel<<<N_NODES * DIM / 256, 256>>>(node, Xhi, Xlo);

    for (int l = 0; l < DEPTH; l++) {
        const float* Xin  = (l == 0) ? node : ((l & 1) ? bufA : bufB);
        float*       Xout = (l == 3) ? out  : ((l & 1) ? bufB : bufA);

        gemm_tc<<<dim3(10, 391), 256, SMEM_BYTES>>>(
            Xhi, Xlo,
            Bhi + (size_t)l * NCOL * DIM,
            Blo + (size_t)l * NCOL * DIM,
            biases + l * DIM,
            H, OUTb);

        edge_kernel<<<N_EDGES / 4, 256>>>(H, OUTb);

        ln_kernel<<<N_NODES / 8, 256>>>(OUTb, Xin, gamma + l * DIM, beta + l * DIM,
                                        Xout, Xhi, Xlo);
    }
}

// round 13
// speedup vs baseline: 1.0008x; 1.0008x over previous
#include <cuda_runtime.h>
#include <cuda_bf16.h>
#include <math.h>
#include <stdint.h>

#define N_NODES 50000
#define N_EDGES 800000
#define DIM     256
#define DEPTH   4
#define N_REL   4
#define LN_EPS  1e-5f
#define NCOL    1280          // 4 relations * 256 + root 256

#define EPB 1024                              // edges per partition block
#define NPB ((N_EDGES + EPB - 1) / EPB)       // 782

typedef __nv_bfloat16 bf16;

// ---------------------------------------------------------------------------
// Scratch (device globals: allocation-free per harness rules)
// ---------------------------------------------------------------------------
__device__ float g_H[(size_t)N_NODES * (N_REL * DIM)];   // per-relation transforms [N,1024]
__device__ float g_OUT[(size_t)N_NODES * DIM];           // agg + X@root + bias
__device__ float g_bufA[(size_t)N_NODES * DIM];          // X ping
__device__ float g_bufB[(size_t)N_NODES * DIM];          // X pong
__device__ bf16  g_Xhi[(size_t)N_NODES * DIM];           // bf16 hi split of X
__device__ bf16  g_Xlo[(size_t)N_NODES * DIM];           // bf16 lo split of X
__device__ bf16  g_Bhi[(size_t)DEPTH * NCOL * DIM];      // W^T hi  [l][n][k]
__device__ bf16  g_Blo[(size_t)DEPTH * NCOL * DIM];      // W^T lo
__device__ int   g_cnt[N_NODES * N_REL];

// edge partition (type-major ordering)
__device__ int   g_blkcnt[N_REL * NPB];
__device__ int   g_blkoff[N_REL * NPB];
__device__ int   g_pgat[N_EDGES];    // src*4 + type  (row in H viewed as [4N,256])
__device__ int   g_pdst[N_EDGES];
__device__ float g_pinv[N_EDGES];

// ---------------------------------------------------------------------------
// PTX helpers (plain sm_80-era instructions -> assemble at target sm_103)
// ---------------------------------------------------------------------------
__device__ __forceinline__ uint32_t smem_u32(const void* p) {
    uint32_t a;
    asm("{ .reg .u64 t; cvta.to.shared.u64 t, %1; cvt.u32.u64 %0, t; }"
        : "=r"(a) : "l"(p));
    return a;
}

__device__ __forceinline__ void ldsm_x4(uint32_t& r0, uint32_t& r1,
                                        uint32_t& r2, uint32_t& r3, uint32_t addr) {
    asm volatile("ldmatrix.sync.aligned.m8n8.x4.shared.b16 {%0,%1,%2,%3}, [%4];"
                 : "=r"(r0), "=r"(r1), "=r"(r2), "=r"(r3) : "r"(addr));
}

#define MMA_BF16(c, a, b0v, b1v)                                             \
    asm volatile(                                                            \
        "mma.sync.aligned.m16n8k16.row.col.f32.bf16.bf16.f32 "               \
        "{%0,%1,%2,%3}, {%4,%5,%6,%7}, {%8,%9}, {%0,%1,%2,%3};"              \
        : "+f"((c)[0]), "+f"((c)[1]), "+f"((c)[2]), "+f"((c)[3])             \
        : "r"((a)[0]), "r"((a)[1]), "r"((a)[2]), "r"((a)[3]),                \
          "r"(b0v), "r"(b1v))

#define CPA16(dst, src)                                                      \
    asm volatile("cp.async.cg.shared.global [%0], [%1], 16;"                 \
                 :: "r"(dst), "l"(src) : "memory")
#define CPA_COMMIT() asm volatile("cp.async.commit_group;" ::: "memory")
#define CPA_WAIT(n)  asm volatile("cp.async.wait_group %0;" :: "n"(n) : "memory")

#define SW(o) ((uint32_t)(o) ^ ((((uint32_t)(o)) >> 3) & 0x70))

// ---------------------------------------------------------------------------
// Setup kernels (once per launch)
// ---------------------------------------------------------------------------
__global__ void zero_cnt_kernel() {
    int i = blockIdx.x * blockDim.x + threadIdx.x;
    if (i < N_NODES * N_REL) g_cnt[i] = 0;
}

__global__ void count_kernel(const int* __restrict__ dst, const int* __restrict__ et) {
    int e = blockIdx.x * blockDim.x + threadIdx.x;
    if (e < N_EDGES) atomicAdd(&g_cnt[dst[e] * N_REL + et[e]], 1);
}

// per-block type histogram
__global__ void hist_kernel(const int* __restrict__ et) {
    __shared__ int sc[N_REL];
    int b = blockIdx.x;
    if (threadIdx.x < N_REL) sc[threadIdx.x] = 0;
    __syncthreads();
    #pragma unroll
    for (int i = 0; i < EPB / 256; i++) {
        int e = b * EPB + threadIdx.x + i * 256;
        if (e < N_EDGES) atomicAdd(&sc[et[e]], 1);
    }
    __syncthreads();
    if (threadIdx.x < N_REL) g_blkcnt[threadIdx.x * NPB + b] = sc[threadIdx.x];
}

// tiny sequential scan (one block)
__global__ void scan_kernel() {
    __shared__ int base[N_REL + 1];
    if (threadIdx.x == 0) {
        int acc = 0;
        base[0] = 0;
        for (int t = 0; t < N_REL; t++) {
            int s = 0;
            for (int b = 0; b < NPB; b++) s += g_blkcnt[t * NPB + b];
            acc += s;
            base[t + 1] = acc;
        }
    }
    __syncthreads();
    int t = threadIdx.x;
    if (t < N_REL) {
        int run = base[t];
        for (int b = 0; b < NPB; b++) {
            g_blkoff[t * NPB + b] = run;
            run += g_blkcnt[t * NPB + b];
        }
    }
}

// scatter edges into type-major order with fused gather index + inv_deg
__global__ void scatter_kernel(const int* __restrict__ src,
                               const int* __restrict__ dst,
                               const int* __restrict__ et) {
    __shared__ int soff[N_REL];
    int b = blockIdx.x;
    if (threadIdx.x < N_REL) soff[threadIdx.x] = g_blkoff[threadIdx.x * NPB + b];
    __syncthreads();
    #pragma unroll
    for (int i = 0; i < EPB / 256; i++) {
        int e = b * EPB + threadIdx.x + i * 256;
        if (e < N_EDGES) {
            int t = et[e];
            int pos = atomicAdd(&soff[t], 1);
            int d = dst[e];
            int c = g_cnt[d * N_REL + t];
            g_pgat[pos] = src[e] * N_REL + t;
            g_pdst[pos] = d;
            g_pinv[pos] = 1.0f / (float)(c > 1 ? c : 1);
        }
    }
}

__device__ __forceinline__ void bf16_split(float x, bf16& h, bf16& l) {
    h = __float2bfloat16(x);
    l = __float2bfloat16(x - __bfloat162float(h));
}

// split node embedding into bf16 hi/lo
__global__ void xsplit_kernel(const float* __restrict__ X,
                              bf16* __restrict__ hi, bf16* __restrict__ lo) {
    int i = blockIdx.x * 256 + threadIdx.x;
    bf16 h, l;
    bf16_split(X[i], h, l);
    hi[i] = h; lo[i] = l;
}

// transpose + split weights: Bhi/Blo[l][n][k] = split(W[l][rel][k][n] or root[l][k][n])
__global__ void wsplit_kernel(const float* __restrict__ W, const float* __restrict__ R,
                              bf16* __restrict__ Bhi, bf16* __restrict__ Blo) {
    __shared__ float t[32][33];
    int l  = blockIdx.z;
    int n0 = blockIdx.x * 32;
    int k0 = blockIdx.y * 32;
    int tx = threadIdx.x, ty = threadIdx.y;   // 32 x 8
    int rel = n0 >> 8;

    #pragma unroll
    for (int j = 0; j < 4; j++) {
        int k = k0 + ty + j * 8;
        float v;
        if (rel < 4)
            v = W[(((size_t)l * 4 + rel) * 256 + k) * 256 + (n0 & 255) + tx];
        else
            v = R[((size_t)l * 256 + k) * 256 + (n0 - 1024) + tx];
        t[ty + j * 8][tx] = v;
    }
    __syncthreads();
    #pragma unroll
    for (int j = 0; j < 4; j++) {
        int n = ty + j * 8;
        float x = t[tx][n];                    // = src[k0+tx][n0+n]
        bf16 h, lo;
        bf16_split(x, h, lo);
        size_t o = ((size_t)l * NCOL + n0 + n) * 256 + k0 + tx;
        Bhi[o] = h;
        Blo[o] = lo;
    }
}

// ---------------------------------------------------------------------------
// bf16 3-product GEMM via mma.sync: C[50000,1280] = X @ Wcat^T
//   C = Xhi*Bhi + Xlo*Bhi + Xhi*Blo  (fp32 accumulate)
// CTA tile 128x128, 8 warps (64x32 each), K chunks of 32 (hi|lo packed in
// one 128B SW128 row), 2-stage cp.async pipeline.
//   col tiles 0..7 -> g_H [N,1024];  col tiles 8..9 -> g_OUT (+bias)
// ---------------------------------------------------------------------------
#define STAGE_BYTES 32768          // A tile 16KB + B tile 16KB
#define SMEM_BYTES  (2 * STAGE_BYTES)

__device__ __forceinline__ void issue_stage(
    uint32_t smBase, int buf, int kc, int row0, int n0, int tid,
    const bf16* __restrict__ Xhi, const bf16* __restrict__ Xlo,
    const bf16* __restrict__ Bhi, const bf16* __restrict__ Blo)
{
    uint32_t aB = smBase + buf * STAGE_BYTES;
    uint32_t bB = aB + 16384;
    #pragma unroll
    for (int t = 0; t < 4; t++) {
        int j   = tid + t * 256;
        int row = j >> 3, ch = j & 7;
        int gr  = row0 + row;
        if (gr > N_NODES - 1) gr = N_NODES - 1;      // clamp; stores are guarded
        const bf16* src = (ch < 4 ? Xhi : Xlo) + (size_t)gr * 256 + kc * 32 + (ch & 3) * 8;
        CPA16(aB + SW(row * 128 + ch * 16), src);
    }
    #pragma unroll
    for (int t = 0; t < 4; t++) {
        int j   = tid + t * 256;
        int row = j >> 3, ch = j & 7;
        const bf16* src = (ch < 4 ? Bhi : Blo) + (size_t)(n0 + row) * 256 + kc * 32 + (ch & 3) * 8;
        CPA16(bB + SW(row * 128 + ch * 16), src);
    }
}

__global__ __launch_bounds__(256) void gemm_tc(
    const bf16* __restrict__ Xhi, const bf16* __restrict__ Xlo,
    const bf16* __restrict__ Bhi, const bf16* __restrict__ Blo,
    const float* __restrict__ bias,
    float* __restrict__ H, float* __restrict__ OUT)
{
    extern __shared__ __align__(1024) char sm[];
    const uint32_t smBase = smem_u32(sm);
    const int tid  = threadIdx.x;
    const int wid  = tid >> 5;
    const int lane = tid & 31;
    const int wm   = wid >> 2;          // 0..1  (64-row slab)
    const int wn   = wid & 3;           // 0..3  (32-col slab)
    const int n0   = blockIdx.x * 128;
    const int row0 = blockIdx.y * 128;

    float acc[4][4][4];
    #pragma unroll
    for (int i = 0; i < 4; i++)
        #pragma unroll
        for (int j = 0; j < 4; j++)
            #pragma unroll
            for (int k = 0; k < 4; k++) acc[i][j][k] = 0.f;

    const int lr  = lane & 7;
    const int ls1 = (lane >> 3) & 1;
    const int ls2 = lane >> 4;

    issue_stage(smBase, 0, 0, row0, n0, tid, Xhi, Xlo, Bhi, Blo);
    CPA_COMMIT();

    int buf = 0;
    for (int kc = 0; kc < 8; kc++) {
        if (kc < 7) {
            issue_stage(smBase, buf ^ 1, kc + 1, row0, n0, tid, Xhi, Xlo, Bhi, Blo);
            CPA_COMMIT();
            CPA_WAIT(1);
        } else {
            CPA_WAIT(0);
        }
        __syncthreads();

        uint32_t aB = smBase + buf * STAGE_BYTES;
        uint32_t bB = aB + 16384;

        #pragma unroll
        for (int kk = 0; kk < 2; kk++) {
            const int ch_hi = 2 * kk;        // 16B chunks 0..3 = hi, 4..7 = lo
            const int ch_lo = 4 + 2 * kk;

            uint32_t ahi[4][4], alo[4][4], bhi[2][4], blo[2][4];

            #pragma unroll
            for (int mf = 0; mf < 4; mf++) {
                int mrow = wm * 64 + mf * 16 + ls1 * 8 + lr;
                int ch   = ch_hi + ls2;
                ldsm_x4(ahi[mf][0], ahi[mf][1], ahi[mf][2], ahi[mf][3],
                        aB + SW(mrow * 128 + ch * 16));
            }
            #pragma unroll
            for (int np = 0; np < 2; np++) {
                int nrow = wn * 32 + np * 16 + ls2 * 8 + lr;
                int ch   = ch_hi + ls1;
                ldsm_x4(bhi[np][0], bhi[np][1], bhi[np][2], bhi[np][3],
                        bB + SW(nrow * 128 + ch * 16));
            }
            #pragma unroll
            for (int mf = 0; mf < 4; mf++)
                #pragma unroll
                for (int nf = 0; nf < 4; nf++)
                    MMA_BF16(acc[mf][nf], ahi[mf],
                             bhi[nf >> 1][(nf & 1) * 2], bhi[nf >> 1][(nf & 1) * 2 + 1]);

            #pragma unroll
            for (int mf = 0; mf < 4; mf++) {
                int mrow = wm * 64 + mf * 16 + ls1 * 8 + lr;
                int ch   = ch_lo + ls2;
                ldsm_x4(alo[mf][0], alo[mf][1], alo[mf][2], alo[mf][3],
                        aB + SW(mrow * 128 + ch * 16));
            }
            #pragma unroll
            for (int mf = 0; mf < 4; mf++)
                #pragma unroll
                for (int nf = 0; nf < 4; nf++)
                    MMA_BF16(acc[mf][nf], alo[mf],
                             bhi[nf >> 1][(nf & 1) * 2], bhi[nf >> 1][(nf & 1) * 2 + 1]);

            #pragma unroll
            for (int np = 0; np < 2; np++) {
                int nrow = wn * 32 + np * 16 + ls2 * 8 + lr;
                int ch   = ch_lo + ls1;
                ldsm_x4(blo[np][0], blo[np][1], blo[np][2], blo[np][3],
                        bB + SW(nrow * 128 + ch * 16));
            }
            #pragma unroll
            for (int mf = 0; mf < 4; mf++)
                #pragma unroll
                for (int nf = 0; nf < 4; nf++)
                    MMA_BF16(acc[mf][nf], ahi[mf],
                             blo[nf >> 1][(nf & 1) * 2], blo[nf >> 1][(nf & 1) * 2 + 1]);
        }
        __syncthreads();
        buf ^= 1;
    }

    // ---- epilogue: direct fp32 stores ----
    const int g  = lane >> 2;
    const int tg = lane & 3;
    const bool isroot = (n0 >= 1024);

    #pragma unroll
    for (int nf = 0; nf < 4; nf++) {
        int col = n0 + wn * 32 + nf * 8 + tg * 2;
        float b0 = 0.f, b1 = 0.f;
        if (isroot) { b0 = bias[col - 1024]; b1 = bias[col - 1023]; }
        #pragma unroll
        for (int mf = 0; mf < 4; mf++) {
            int r0 = row0 + wm * 64 + mf * 16 + g;
            int r1 = r0 + 8;
            float2 v0 = make_float2(acc[mf][nf][0] + b0, acc[mf][nf][1] + b1);
            float2 v1 = make_float2(acc[mf][nf][2] + b0, acc[mf][nf][3] + b1);
            if (isroot) {
                if (r0 < N_NODES) *(float2*)(OUT + (size_t)r0 * 256 + col - 1024) = v0;
                if (r1 < N_NODES) *(float2*)(OUT + (size_t)r1 * 256 + col - 1024) = v1;
            } else {
                if (r0 < N_NODES) *(float2*)(H + (size_t)r0 * 1024 + col) = v0;
                if (r1 < N_NODES) *(float2*)(H + (size_t)r1 * 1024 + col) = v1;
            }
        }
    }
}

// ---------------------------------------------------------------------------
// Edge aggregation (type-major partitioned): OUT[dst] += inv * H[gat]
// Gather source per type is 51MB -> L2 resident.
// ---------------------------------------------------------------------------
__global__ void edge_kernel(const float* __restrict__ H,
                            float* __restrict__ OUT)
{
    int e    = blockIdx.x * 4 + (threadIdx.x >> 6);
    int lane = threadIdx.x & 63;

    int   g   = g_pgat[e];
    int   d   = g_pdst[e];
    float inv = g_pinv[e];

    float4 v = *(const float4*)(H + (size_t)g * DIM + lane * 4);
    v.x *= inv; v.y *= inv; v.z *= inv; v.w *= inv;

    float* p = OUT + (size_t)d * DIM + lane * 4;
    asm volatile("red.global.add.v4.f32 [%0], {%1, %2, %3, %4};"
                 :: "l"(p), "f"(v.x), "f"(v.y), "f"(v.z), "f"(v.w)
                 : "memory");
}

// ---------------------------------------------------------------------------
// LayerNorm + ELU + residual (warp per row, 8 floats/lane), fused bf16 split
// ---------------------------------------------------------------------------
__global__ __launch_bounds__(256) void ln_kernel(
        const float* __restrict__ OUT,
        const float* __restrict__ Xin,
        const float* __restrict__ gamma,
        const float* __restrict__ beta,
        float* __restrict__ Xout,
        bf16* __restrict__ Xhi,
        bf16* __restrict__ Xlo)
{
    int row  = blockIdx.x * 8 + (threadIdx.x >> 5);
    int lane = threadIdx.x & 31;
    size_t base = (size_t)row * DIM + lane * 8;

    float v[8];
    *(float4*)&v[0] = *(const float4*)(OUT + base);
    *(float4*)&v[4] = *(const float4*)(OUT + base + 4);

    float s = v[0] + v[1] + v[2] + v[3] + v[4] + v[5] + v[6] + v[7];
    #pragma unroll
    for (int o = 16; o > 0; o >>= 1) s += __shfl_xor_sync(0xffffffffu, s, o);
    float mu = s * (1.0f / DIM);

    float q = 0.f;
    #pragma unroll
    for (int k = 0; k < 8; k++) { float dl = v[k] - mu; q += dl * dl; }
    #pragma unroll
    for (int o = 16; o > 0; o >>= 1) q += __shfl_xor_sync(0xffffffffu, q, o);
    float rstd = rsqrtf(q * (1.0f / DIM) + LN_EPS);

    float gmv[8], btv[8], xi[8];
    *(float4*)&gmv[0] = *(const float4*)(gamma + lane * 8);
    *(float4*)&gmv[4] = *(const float4*)(gamma + lane * 8 + 4);
    *(float4*)&btv[0] = *(const float4*)(beta + lane * 8);
    *(float4*)&btv[4] = *(const float4*)(beta + lane * 8 + 4);
    *(float4*)&xi[0]  = *(const float4*)(Xin + base);
    *(float4*)&xi[4]  = *(const float4*)(Xin + base + 4);

    float r[8];
    ushort hi[8], lo[8];
    #pragma unroll
    for (int k = 0; k < 8; k++) {
        float y = (v[k] - mu) * rstd * gmv[k] + btv[k];
        y = (y > 0.f) ? y : expm1f(y);
        r[k] = y + xi[k];
        bf16 h, l;
        bf16_split(r[k], h, l);
        hi[k] = __bfloat16_as_ushort(h);
        lo[k] = __bfloat16_as_ushort(l);
    }

    *(float4*)(Xout + base)     = *(float4*)&r[0];
    *(float4*)(Xout + base + 4) = *(float4*)&r[4];
    *(uint4*)(Xhi + base) = *(uint4*)&hi[0];
    *(uint4*)(Xlo + base) = *(uint4*)&lo[0];
}

// ---------------------------------------------------------------------------
// Driver
// ---------------------------------------------------------------------------
extern "C" void kernel_launch(void* const* d_in, const int* in_sizes, int n_in,
                              void* d_out, int out_size)
{
    const float* node    = (const float*)d_in[0];
    const float* weights = (const float*)d_in[1];   // [4,4,256,256]
    const float* roots   = (const float*)d_in[2];   // [4,256,256]
    const float* biases  = (const float*)d_in[3];   // [4,256]
    const float* gamma   = (const float*)d_in[4];   // [4,256]
    const float* beta    = (const float*)d_in[5];   // [4,256]
    const int*   eidx    = (const int*)d_in[6];     // [2,800000]
    const int*   etype   = (const int*)d_in[7];     // [800000]
    const int*   srcv    = eidx;
    const int*   dstv    = eidx + N_EDGES;
    float*       out     = (float*)d_out;

    float *H, *OUTb, *bufA, *bufB;
    bf16 *Xhi, *Xlo, *Bhi, *Blo;
    cudaGetSymbolAddress((void**)&H,    g_H);
    cudaGetSymbolAddress((void**)&OUTb, g_OUT);
    cudaGetSymbolAddress((void**)&bufA, g_bufA);
    cudaGetSymbolAddress((void**)&bufB, g_bufB);
    cudaGetSymbolAddress((void**)&Xhi,  g_Xhi);
    cudaGetSymbolAddress((void**)&Xlo,  g_Xlo);
    cudaGetSymbolAddress((void**)&Bhi,  g_Bhi);
    cudaGetSymbolAddress((void**)&Blo,  g_Blo);

    static int smem_set = 0;
    if (!smem_set) {
        cudaFuncSetAttribute(gemm_tc, cudaFuncAttributeMaxDynamicSharedMemorySize, SMEM_BYTES);
        smem_set = 1;
    }

    // once per launch: degree histogram, edge partition, operand splits
    zero_cnt_kernel<<<(N_NODES * N_REL + 255) / 256, 256>>>();
    count_kernel<<<(N_EDGES + 255) / 256, 256>>>(dstv, etype);
    hist_kernel<<<NPB, 256>>>(etype);
    scan_kernel<<<1, 32>>>();
    scatter_kernel<<<NPB, 256>>>(srcv, dstv, etype);
    wsplit_kernel<<<dim3(NCOL / 32, DIM / 32, DEPTH), dim3(32, 8)>>>(weights, roots, Bhi, Blo);
    xsplit_kernel<<<N_NODES * DIM / 256, 256>>>(node, Xhi, Xlo);

    for (int l = 0; l < DEPTH; l++) {
        const float* Xin  = (l == 0) ? node : ((l & 1) ? bufA : bufB);
        float*       Xout = (l == 3) ? out  : ((l & 1) ? bufB : bufA);

        gemm_tc<<<dim3(10, 391), 256, SMEM_BYTES>>>(
            Xhi, Xlo,
            Bhi + (size_t)l * NCOL * DIM,
            Blo + (size_t)l * NCOL * DIM,
            biases + l * DIM,
            H, OUTb);

        edge_kernel<<<N_EDGES / 4, 256>>>(H, OUTb);

        ln_kernel<<<N_NODES / 8, 256>>>(OUTb, Xin, gamma + l * DIM, beta + l * DIM,
                                        Xout, Xhi, Xlo);
    }
}

// round 14
// speedup vs baseline: 1.0013x; 1.0005x over previous
#include <cuda_runtime.h>
#include <cuda_bf16.h>
#include <math.h>
#include <stdint.h>

#define N_NODES 50000
#define N_EDGES 800000
#define DIM     256
#define DEPTH   4
#define N_REL   4
#define LN_EPS  1e-5f
#define NCOL    1280          // 4 relations * 256 + root 256

#define EPB 1024                              // edges per partition block
#define NPB ((N_EDGES + EPB - 1) / EPB)       // 782

typedef __nv_bfloat16 bf16;

// ---------------------------------------------------------------------------
// Scratch (device globals: allocation-free per harness rules)
// ---------------------------------------------------------------------------
__device__ float g_H[(size_t)N_NODES * (N_REL * DIM)];   // per-relation transforms [N,1024]
__device__ float g_OUT[(size_t)N_NODES * DIM];           // agg + X@root + bias
__device__ float g_bufA[(size_t)N_NODES * DIM];          // X ping
__device__ float g_bufB[(size_t)N_NODES * DIM];          // X pong
__device__ bf16  g_Xhi[(size_t)N_NODES * DIM];           // bf16 hi split of X
__device__ bf16  g_Xlo[(size_t)N_NODES * DIM];           // bf16 lo split of X
__device__ bf16  g_Bhi[(size_t)DEPTH * NCOL * DIM];      // W^T hi  [l][n][k]
__device__ bf16  g_Blo[(size_t)DEPTH * NCOL * DIM];      // W^T lo
__device__ int   g_cnt[N_NODES * N_REL];

// edge partition (type-major ordering)
__device__ int   g_blkcnt[N_REL * NPB];
__device__ int   g_blkoff[N_REL * NPB];
__device__ int   g_pgat[N_EDGES];    // src*4 + type  (row in H viewed as [4N,256])
__device__ int   g_pdst[N_EDGES];
__device__ float g_pinv[N_EDGES];

// ---------------------------------------------------------------------------
// PTX helpers (plain sm_80-era instructions -> assemble at target sm_103)
// ---------------------------------------------------------------------------
__device__ __forceinline__ uint32_t smem_u32(const void* p) {
    uint32_t a;
    asm("{ .reg .u64 t; cvta.to.shared.u64 t, %1; cvt.u32.u64 %0, t; }"
        : "=r"(a) : "l"(p));
    return a;
}

__device__ __forceinline__ void ldsm_x4(uint32_t& r0, uint32_t& r1,
                                        uint32_t& r2, uint32_t& r3, uint32_t addr) {
    asm volatile("ldmatrix.sync.aligned.m8n8.x4.shared.b16 {%0,%1,%2,%3}, [%4];"
                 : "=r"(r0), "=r"(r1), "=r"(r2), "=r"(r3) : "r"(addr));
}

#define MMA_BF16(c, a, b0v, b1v)                                             \
    asm volatile(                                                            \
        "mma.sync.aligned.m16n8k16.row.col.f32.bf16.bf16.f32 "               \
        "{%0,%1,%2,%3}, {%4,%5,%6,%7}, {%8,%9}, {%0,%1,%2,%3};"              \
        : "+f"((c)[0]), "+f"((c)[1]), "+f"((c)[2]), "+f"((c)[3])             \
        : "r"((a)[0]), "r"((a)[1]), "r"((a)[2]), "r"((a)[3]),                \
          "r"(b0v), "r"(b1v))

#define CPA16(dst, src)                                                      \
    asm volatile("cp.async.cg.shared.global [%0], [%1], 16;"                 \
                 :: "r"(dst), "l"(src) : "memory")
#define CPA_COMMIT() asm volatile("cp.async.commit_group;" ::: "memory")
#define CPA_WAIT(n)  asm volatile("cp.async.wait_group %0;" :: "n"(n) : "memory")

#define SW(o) ((uint32_t)(o) ^ ((((uint32_t)(o)) >> 3) & 0x70))

// ---------------------------------------------------------------------------
// Setup kernels (once per launch)
// ---------------------------------------------------------------------------
__global__ void zero_cnt_kernel() {
    int i = blockIdx.x * blockDim.x + threadIdx.x;
    if (i < N_NODES * N_REL) g_cnt[i] = 0;
}

__global__ void count_kernel(const int* __restrict__ dst, const int* __restrict__ et) {
    int e = blockIdx.x * blockDim.x + threadIdx.x;
    if (e < N_EDGES) atomicAdd(&g_cnt[dst[e] * N_REL + et[e]], 1);
}

// per-block type histogram
__global__ void hist_kernel(const int* __restrict__ et) {
    __shared__ int sc[N_REL];
    int b = blockIdx.x;
    if (threadIdx.x < N_REL) sc[threadIdx.x] = 0;
    __syncthreads();
    #pragma unroll
    for (int i = 0; i < EPB / 256; i++) {
        int e = b * EPB + threadIdx.x + i * 256;
        if (e < N_EDGES) atomicAdd(&sc[et[e]], 1);
    }
    __syncthreads();
    if (threadIdx.x < N_REL) g_blkcnt[threadIdx.x * NPB + b] = sc[threadIdx.x];
}

// tiny sequential scan (one block)
__global__ void scan_kernel() {
    __shared__ int base[N_REL + 1];
    if (threadIdx.x == 0) {
        int acc = 0;
        base[0] = 0;
        for (int t = 0; t < N_REL; t++) {
            int s = 0;
            for (int b = 0; b < NPB; b++) s += g_blkcnt[t * NPB + b];
            acc += s;
            base[t + 1] = acc;
        }
    }
    __syncthreads();
    int t = threadIdx.x;
    if (t < N_REL) {
        int run = base[t];
        for (int b = 0; b < NPB; b++) {
            g_blkoff[t * NPB + b] = run;
            run += g_blkcnt[t * NPB + b];
        }
    }
}

// scatter edges into type-major order with fused gather index + inv_deg
__global__ void scatter_kernel(const int* __restrict__ src,
                               const int* __restrict__ dst,
                               const int* __restrict__ et) {
    __shared__ int soff[N_REL];
    int b = blockIdx.x;
    if (threadIdx.x < N_REL) soff[threadIdx.x] = g_blkoff[threadIdx.x * NPB + b];
    __syncthreads();
    #pragma unroll
    for (int i = 0; i < EPB / 256; i++) {
        int e = b * EPB + threadIdx.x + i * 256;
        if (e < N_EDGES) {
            int t = et[e];
            int pos = atomicAdd(&soff[t], 1);
            int d = dst[e];
            int c = g_cnt[d * N_REL + t];
            g_pgat[pos] = src[e] * N_REL + t;
            g_pdst[pos] = d;
            g_pinv[pos] = 1.0f / (float)(c > 1 ? c : 1);
        }
    }
}

__device__ __forceinline__ void bf16_split(float x, bf16& h, bf16& l) {
    h = __float2bfloat16(x);
    l = __float2bfloat16(x - __bfloat162float(h));
}

// split node embedding into bf16 hi/lo
__global__ void xsplit_kernel(const float* __restrict__ X,
                              bf16* __restrict__ hi, bf16* __restrict__ lo) {
    int i = blockIdx.x * 256 + threadIdx.x;
    bf16 h, l;
    bf16_split(X[i], h, l);
    hi[i] = h; lo[i] = l;
}

// transpose + split weights: Bhi/Blo[l][n][k] = split(W[l][rel][k][n] or root[l][k][n])
__global__ void wsplit_kernel(const float* __restrict__ W, const float* __restrict__ R,
                              bf16* __restrict__ Bhi, bf16* __restrict__ Blo) {
    __shared__ float t[32][33];
    int l  = blockIdx.z;
    int n0 = blockIdx.x * 32;
    int k0 = blockIdx.y * 32;
    int tx = threadIdx.x, ty = threadIdx.y;   // 32 x 8
    int rel = n0 >> 8;

    #pragma unroll
    for (int j = 0; j < 4; j++) {
        int k = k0 + ty + j * 8;
        float v;
        if (rel < 4)
            v = W[(((size_t)l * 4 + rel) * 256 + k) * 256 + (n0 & 255) + tx];
        else
            v = R[((size_t)l * 256 + k) * 256 + (n0 - 1024) + tx];
        t[ty + j * 8][tx] = v;
    }
    __syncthreads();
    #pragma unroll
    for (int j = 0; j < 4; j++) {
        int n = ty + j * 8;
        float x = t[tx][n];                    // = src[k0+tx][n0+n]
        bf16 h, lo;
        bf16_split(x, h, lo);
        size_t o = ((size_t)l * NCOL + n0 + n) * 256 + k0 + tx;
        Bhi[o] = h;
        Blo[o] = lo;
    }
}

// ---------------------------------------------------------------------------
// bf16 3-product GEMM via mma.sync: C[50000,1280] = X @ Wcat^T
//   C = Xhi*Bhi + Xlo*Bhi + Xhi*Blo  (fp32 accumulate)
// CTA tile 128x128, 8 warps (64x32 each), K chunks of 32 (hi|lo packed in
// one 128B SW128 row), 2-stage cp.async pipeline.
//   col tiles 0..7 -> g_H [N,1024];  col tiles 8..9 -> g_OUT (+bias)
// ---------------------------------------------------------------------------
#define STAGE_BYTES 32768          // A tile 16KB + B tile 16KB
#define SMEM_BYTES  (2 * STAGE_BYTES)

__device__ __forceinline__ void issue_stage(
    uint32_t smBase, int buf, int kc, int row0, int n0, int tid,
    const bf16* __restrict__ Xhi, const bf16* __restrict__ Xlo,
    const bf16* __restrict__ Bhi, const bf16* __restrict__ Blo)
{
    uint32_t aB = smBase + buf * STAGE_BYTES;
    uint32_t bB = aB + 16384;
    #pragma unroll
    for (int t = 0; t < 4; t++) {
        int j   = tid + t * 256;
        int row = j >> 3, ch = j & 7;
        int gr  = row0 + row;
        if (gr > N_NODES - 1) gr = N_NODES - 1;      // clamp; stores are guarded
        const bf16* src = (ch < 4 ? Xhi : Xlo) + (size_t)gr * 256 + kc * 32 + (ch & 3) * 8;
        CPA16(aB + SW(row * 128 + ch * 16), src);
    }
    #pragma unroll
    for (int t = 0; t < 4; t++) {
        int j   = tid + t * 256;
        int row = j >> 3, ch = j & 7;
        const bf16* src = (ch < 4 ? Bhi : Blo) + (size_t)(n0 + row) * 256 + kc * 32 + (ch & 3) * 8;
        CPA16(bB + SW(row * 128 + ch * 16), src);
    }
}

__global__ __launch_bounds__(256) void gemm_tc(
    const bf16* __restrict__ Xhi, const bf16* __restrict__ Xlo,
    const bf16* __restrict__ Bhi, const bf16* __restrict__ Blo,
    const float* __restrict__ bias,
    float* __restrict__ H, float* __restrict__ OUT)
{
    extern __shared__ __align__(1024) char sm[];
    const uint32_t smBase = smem_u32(sm);
    const int tid  = threadIdx.x;
    const int wid  = tid >> 5;
    const int lane = tid & 31;
    const int wm   = wid >> 2;          // 0..1  (64-row slab)
    const int wn   = wid & 3;           // 0..3  (32-col slab)
    const int n0   = blockIdx.x * 128;
    const int row0 = blockIdx.y * 128;

    float acc[4][4][4];
    #pragma unroll
    for (int i = 0; i < 4; i++)
        #pragma unroll
        for (int j = 0; j < 4; j++)
            #pragma unroll
            for (int k = 0; k < 4; k++) acc[i][j][k] = 0.f;

    const int lr  = lane & 7;
    const int ls1 = (lane >> 3) & 1;
    const int ls2 = lane >> 4;

    issue_stage(smBase, 0, 0, row0, n0, tid, Xhi, Xlo, Bhi, Blo);
    CPA_COMMIT();

    int buf = 0;
    for (int kc = 0; kc < 8; kc++) {
        if (kc < 7) {
            issue_stage(smBase, buf ^ 1, kc + 1, row0, n0, tid, Xhi, Xlo, Bhi, Blo);
            CPA_COMMIT();
            CPA_WAIT(1);
        } else {
            CPA_WAIT(0);
        }
        __syncthreads();

        uint32_t aB = smBase + buf * STAGE_BYTES;
        uint32_t bB = aB + 16384;

        #pragma unroll
        for (int kk = 0; kk < 2; kk++) {
            const int ch_hi = 2 * kk;        // 16B chunks 0..3 = hi, 4..7 = lo
            const int ch_lo = 4 + 2 * kk;

            uint32_t ahi[4][4], alo[4][4], bhi[2][4], blo[2][4];

            #pragma unroll
            for (int mf = 0; mf < 4; mf++) {
                int mrow = wm * 64 + mf * 16 + ls1 * 8 + lr;
                int ch   = ch_hi + ls2;
                ldsm_x4(ahi[mf][0], ahi[mf][1], ahi[mf][2], ahi[mf][3],
                        aB + SW(mrow * 128 + ch * 16));
            }
            #pragma unroll
            for (int np = 0; np < 2; np++) {
                int nrow = wn * 32 + np * 16 + ls2 * 8 + lr;
                int ch   = ch_hi + ls1;
                ldsm_x4(bhi[np][0], bhi[np][1], bhi[np][2], bhi[np][3],
                        bB + SW(nrow * 128 + ch * 16));
            }
            #pragma unroll
            for (int mf = 0; mf < 4; mf++)
                #pragma unroll
                for (int nf = 0; nf < 4; nf++)
                    MMA_BF16(acc[mf][nf], ahi[mf],
                             bhi[nf >> 1][(nf & 1) * 2], bhi[nf >> 1][(nf & 1) * 2 + 1]);

            #pragma unroll
            for (int mf = 0; mf < 4; mf++) {
                int mrow = wm * 64 + mf * 16 + ls1 * 8 + lr;
                int ch   = ch_lo + ls2;
                ldsm_x4(alo[mf][0], alo[mf][1], alo[mf][2], alo[mf][3],
                        aB + SW(mrow * 128 + ch * 16));
            }
            #pragma unroll
            for (int mf = 0; mf < 4; mf++)
                #pragma unroll
                for (int nf = 0; nf < 4; nf++)
                    MMA_BF16(acc[mf][nf], alo[mf],
                             bhi[nf >> 1][(nf & 1) * 2], bhi[nf >> 1][(nf & 1) * 2 + 1]);

            #pragma unroll
            for (int np = 0; np < 2; np++) {
                int nrow = wn * 32 + np * 16 + ls2 * 8 + lr;
                int ch   = ch_lo + ls1;
                ldsm_x4(blo[np][0], blo[np][1], blo[np][2], blo[np][3],
                        bB + SW(nrow * 128 + ch * 16));
            }
            #pragma unroll
            for (int mf = 0; mf < 4; mf++)
                #pragma unroll
                for (int nf = 0; nf < 4; nf++)
                    MMA_BF16(acc[mf][nf], ahi[mf],
                             blo[nf >> 1][(nf & 1) * 2], blo[nf >> 1][(nf & 1) * 2 + 1]);
        }
        __syncthreads();
        buf ^= 1;
    }

    // ---- epilogue: direct fp32 stores ----
    const int g  = lane >> 2;
    const int tg = lane & 3;
    const bool isroot = (n0 >= 1024);

    #pragma unroll
    for (int nf = 0; nf < 4; nf++) {
        int col = n0 + wn * 32 + nf * 8 + tg * 2;
        float b0 = 0.f, b1 = 0.f;
        if (isroot) { b0 = bias[col - 1024]; b1 = bias[col - 1023]; }
        #pragma unroll
        for (int mf = 0; mf < 4; mf++) {
            int r0 = row0 + wm * 64 + mf * 16 + g;
            int r1 = r0 + 8;
            float2 v0 = make_float2(acc[mf][nf][0] + b0, acc[mf][nf][1] + b1);
            float2 v1 = make_float2(acc[mf][nf][2] + b0, acc[mf][nf][3] + b1);
            if (isroot) {
                if (r0 < N_NODES) *(float2*)(OUT + (size_t)r0 * 256 + col - 1024) = v0;
                if (r1 < N_NODES) *(float2*)(OUT + (size_t)r1 * 256 + col - 1024) = v1;
            } else {
                if (r0 < N_NODES) *(float2*)(H + (size_t)r0 * 1024 + col) = v0;
                if (r1 < N_NODES) *(float2*)(H + (size_t)r1 * 1024 + col) = v1;
            }
        }
    }
}

// ---------------------------------------------------------------------------
// Edge aggregation (type-major partitioned): OUT[dst] += inv * H[gat]
// Gather source per type is 51MB -> L2 resident.
// ---------------------------------------------------------------------------
__global__ void edge_kernel(const float* __restrict__ H,
                            float* __restrict__ OUT)
{
    int e    = blockIdx.x * 4 + (threadIdx.x >> 6);
    int lane = threadIdx.x & 63;

    int   g   = g_pgat[e];
    int   d   = g_pdst[e];
    float inv = g_pinv[e];

    float4 v = *(const float4*)(H + (size_t)g * DIM + lane * 4);
    v.x *= inv; v.y *= inv; v.z *= inv; v.w *= inv;

    float* p = OUT + (size_t)d * DIM + lane * 4;
    asm volatile("red.global.add.v4.f32 [%0], {%1, %2, %3, %4};"
                 :: "l"(p), "f"(v.x), "f"(v.y), "f"(v.z), "f"(v.w)
                 : "memory");
}

// ---------------------------------------------------------------------------
// LayerNorm + ELU + residual (warp per row, 8 floats/lane), fused bf16 split
// ---------------------------------------------------------------------------
__global__ __launch_bounds__(256) void ln_kernel(
        const float* __restrict__ OUT,
        const float* __restrict__ Xin,
        const float* __restrict__ gamma,
        const float* __restrict__ beta,
        float* __restrict__ Xout,
        bf16* __restrict__ Xhi,
        bf16* __restrict__ Xlo)
{
    int row  = blockIdx.x * 8 + (threadIdx.x >> 5);
    int lane = threadIdx.x & 31;
    size_t base = (size_t)row * DIM + lane * 8;

    float v[8];
    *(float4*)&v[0] = *(const float4*)(OUT + base);
    *(float4*)&v[4] = *(const float4*)(OUT + base + 4);

    float s = v[0] + v[1] + v[2] + v[3] + v[4] + v[5] + v[6] + v[7];
    #pragma unroll
    for (int o = 16; o > 0; o >>= 1) s += __shfl_xor_sync(0xffffffffu, s, o);
    float mu = s * (1.0f / DIM);

    float q = 0.f;
    #pragma unroll
    for (int k = 0; k < 8; k++) { float dl = v[k] - mu; q += dl * dl; }
    #pragma unroll
    for (int o = 16; o > 0; o >>= 1) q += __shfl_xor_sync(0xffffffffu, q, o);
    float rstd = rsqrtf(q * (1.0f / DIM) + LN_EPS);

    float gmv[8], btv[8], xi[8];
    *(float4*)&gmv[0] = *(const float4*)(gamma + lane * 8);
    *(float4*)&gmv[4] = *(const float4*)(gamma + lane * 8 + 4);
    *(float4*)&btv[0] = *(const float4*)(beta + lane * 8);
    *(float4*)&btv[4] = *(const float4*)(beta + lane * 8 + 4);
    *(float4*)&xi[0]  = *(const float4*)(Xin + base);
    *(float4*)&xi[4]  = *(const float4*)(Xin + base + 4);

    float r[8];
    ushort hi[8], lo[8];
    #pragma unroll
    for (int k = 0; k < 8; k++) {
        float y = (v[k] - mu) * rstd * gmv[k] + btv[k];
        y = (y > 0.f) ? y : expm1f(y);
        r[k] = y + xi[k];
        bf16 h, l;
        bf16_split(r[k], h, l);
        hi[k] = __bfloat16_as_ushort(h);
        lo[k] = __bfloat16_as_ushort(l);
    }

    *(float4*)(Xout + base)     = *(float4*)&r[0];
    *(float4*)(Xout + base + 4) = *(float4*)&r[4];
    *(uint4*)(Xhi + base) = *(uint4*)&hi[0];
    *(uint4*)(Xlo + base) = *(uint4*)&lo[0];
}

// ---------------------------------------------------------------------------
// Driver
// ---------------------------------------------------------------------------
extern "C" void kernel_launch(void* const* d_in, const int* in_sizes, int n_in,
                              void* d_out, int out_size)
{
    const float* node    = (const float*)d_in[0];
    const float* weights = (const float*)d_in[1];   // [4,4,256,256]
    const float* roots   = (const float*)d_in[2];   // [4,256,256]
    const float* biases  = (const float*)d_in[3];   // [4,256]
    const float* gamma   = (const float*)d_in[4];   // [4,256]
    const float* beta    = (const float*)d_in[5];   // [4,256]
    const int*   eidx    = (const int*)d_in[6];     // [2,800000]
    const int*   etype   = (const int*)d_in[7];     // [800000]
    const int*   srcv    = eidx;
    const int*   dstv    = eidx + N_EDGES;
    float*       out     = (float*)d_out;

    float *H, *OUTb, *bufA, *bufB;
    bf16 *Xhi, *Xlo, *Bhi, *Blo;
    cudaGetSymbolAddress((void**)&H,    g_H);
    cudaGetSymbolAddress((void**)&OUTb, g_OUT);
    cudaGetSymbolAddress((void**)&bufA, g_bufA);
    cudaGetSymbolAddress((void**)&bufB, g_bufB);
    cudaGetSymbolAddress((void**)&Xhi,  g_Xhi);
    cudaGetSymbolAddress((void**)&Xlo,  g_Xlo);
    cudaGetSymbolAddress((void**)&Bhi,  g_Bhi);
    cudaGetSymbolAddress((void**)&Blo,  g_Blo);

    static int smem_set = 0;
    if (!smem_set) {
        cudaFuncSetAttribute(gemm_tc, cudaFuncAttributeMaxDynamicSharedMemorySize, SMEM_BYTES);
        smem_set = 1;
    }

    // once per launch: degree histogram, edge partition, operand splits
    zero_cnt_kernel<<<(N_NODES * N_REL + 255) / 256, 256>>>();
    count_kernel<<<(N_EDGES + 255) / 256, 256>>>(dstv, etype);
    hist_kernel<<<NPB, 256>>>(etype);
    scan_kernel<<<1, 32>>>();
    scatter_kernel<<<NPB, 256>>>(srcv, dstv, etype);
    wsplit_kernel<<<dim3(NCOL / 32, DIM / 32, DEPTH), dim3(32, 8)>>>(weights, roots, Bhi, Blo);
    xsplit_kernel<<<N_NODES * DIM / 256, 256>>>(node, Xhi, Xlo);

    for (int l = 0; l < DEPTH; l++) {
        const float* Xin  = (l == 0) ? node : ((l & 1) ? bufA : bufB);
        float*       Xout = (l == 3) ? out  : ((l & 1) ? bufB : bufA);

        gemm_tc<<<dim3(10, 391), 256, SMEM_BYTES>>>(
            Xhi, Xlo,
            Bhi + (size_t)l * NCOL * DIM,
            Blo + (size_t)l * NCOL * DIM,
            biases + l * DIM,
            H, OUTb);

        edge_kernel<<<N_EDGES / 4, 256>>>(H, OUTb);

        ln_kernel<<<N_NODES / 8, 256>>>(OUTb, Xin, gamma + l * DIM, beta + l * DIM,
                                        Xout, Xhi, Xlo);
    }
}

// round 15
// speedup vs baseline: 1.0054x; 1.0041x over previous
#include <cuda_runtime.h>
#include <cuda_bf16.h>
#include <math.h>
#include <stdint.h>

#define N_NODES 50000
#define N_EDGES 800000
#define DIM     256
#define DEPTH   4
#define N_REL   4
#define LN_EPS  1e-5f
#define NCOL    1280          // 4 relations * 256 + root 256

#define EPB 1024                              // edges per partition block
#define NPB ((N_EDGES + EPB - 1) / EPB)       // 782

typedef __nv_bfloat16 bf16;

// ---------------------------------------------------------------------------
// Scratch (device globals: allocation-free per harness rules)
// ---------------------------------------------------------------------------
__device__ float g_H[(size_t)N_NODES * (N_REL * DIM)];   // per-relation transforms [N,1024]
__device__ float g_OUT[(size_t)N_NODES * DIM];           // agg + X@root + bias
__device__ float g_bufA[(size_t)N_NODES * DIM];          // X ping
__device__ float g_bufB[(size_t)N_NODES * DIM];          // X pong
__device__ bf16  g_Xhi[(size_t)N_NODES * DIM];           // bf16 hi split of X
__device__ bf16  g_Xlo[(size_t)N_NODES * DIM];           // bf16 lo split of X
__device__ bf16  g_Bhi[(size_t)DEPTH * NCOL * DIM];      // W^T hi  [l][n][k]
__device__ bf16  g_Blo[(size_t)DEPTH * NCOL * DIM];      // W^T lo
__device__ int   g_cnt[N_NODES * N_REL];

// edge partition (type-major ordering)
__device__ int   g_blkcnt[N_REL * NPB];
__device__ int   g_blkoff[N_REL * NPB];
__device__ int   g_pgat[N_EDGES];    // src*4 + type  (row in H viewed as [4N,256])
__device__ int   g_pdst[N_EDGES];
__device__ float g_pinv[N_EDGES];

// ---------------------------------------------------------------------------
// PTX helpers (plain sm_80-era instructions -> assemble at target sm_103)
// ---------------------------------------------------------------------------
__device__ __forceinline__ uint32_t smem_u32(const void* p) {
    uint32_t a;
    asm("{ .reg .u64 t; cvta.to.shared.u64 t, %1; cvt.u32.u64 %0, t; }"
        : "=r"(a) : "l"(p));
    return a;
}

__device__ __forceinline__ void ldsm_x4(uint32_t& r0, uint32_t& r1,
                                        uint32_t& r2, uint32_t& r3, uint32_t addr) {
    asm volatile("ldmatrix.sync.aligned.m8n8.x4.shared.b16 {%0,%1,%2,%3}, [%4];"
                 : "=r"(r0), "=r"(r1), "=r"(r2), "=r"(r3) : "r"(addr));
}

#define MMA_BF16(c, a, b0v, b1v)                                             \
    asm volatile(                                                            \
        "mma.sync.aligned.m16n8k16.row.col.f32.bf16.bf16.f32 "               \
        "{%0,%1,%2,%3}, {%4,%5,%6,%7}, {%8,%9}, {%0,%1,%2,%3};"              \
        : "+f"((c)[0]), "+f"((c)[1]), "+f"((c)[2]), "+f"((c)[3])             \
        : "r"((a)[0]), "r"((a)[1]), "r"((a)[2]), "r"((a)[3]),                \
          "r"(b0v), "r"(b1v))

#define CPA16(dst, src)                                                      \
    asm volatile("cp.async.cg.shared.global [%0], [%1], 16;"                 \
                 :: "r"(dst), "l"(src) : "memory")
#define CPA_COMMIT() asm volatile("cp.async.commit_group;" ::: "memory")
#define CPA_WAIT(n)  asm volatile("cp.async.wait_group %0;" :: "n"(n) : "memory")

#define SW(o) ((uint32_t)(o) ^ ((((uint32_t)(o)) >> 3) & 0x70))

// ---------------------------------------------------------------------------
// Setup kernels (once per launch)
// ---------------------------------------------------------------------------
__global__ void zero_cnt_kernel() {
    int i = blockIdx.x * blockDim.x + threadIdx.x;
    if (i < N_NODES * N_REL) g_cnt[i] = 0;
}

__global__ void count_kernel(const int* __restrict__ dst, const int* __restrict__ et) {
    int e = blockIdx.x * blockDim.x + threadIdx.x;
    if (e < N_EDGES) atomicAdd(&g_cnt[dst[e] * N_REL + et[e]], 1);
}

// per-block type histogram
__global__ void hist_kernel(const int* __restrict__ et) {
    __shared__ int sc[N_REL];
    int b = blockIdx.x;
    if (threadIdx.x < N_REL) sc[threadIdx.x] = 0;
    __syncthreads();
    #pragma unroll
    for (int i = 0; i < EPB / 256; i++) {
        int e = b * EPB + threadIdx.x + i * 256;
        if (e < N_EDGES) atomicAdd(&sc[et[e]], 1);
    }
    __syncthreads();
    if (threadIdx.x < N_REL) g_blkcnt[threadIdx.x * NPB + b] = sc[threadIdx.x];
}

// tiny sequential scan (one block)
__global__ void scan_kernel() {
    __shared__ int base[N_REL + 1];
    if (threadIdx.x == 0) {
        int acc = 0;
        base[0] = 0;
        for (int t = 0; t < N_REL; t++) {
            int s = 0;
            for (int b = 0; b < NPB; b++) s += g_blkcnt[t * NPB + b];
            acc += s;
            base[t + 1] = acc;
        }
    }
    __syncthreads();
    int t = threadIdx.x;
    if (t < N_REL) {
        int run = base[t];
        for (int b = 0; b < NPB; b++) {
            g_blkoff[t * NPB + b] = run;
            run += g_blkcnt[t * NPB + b];
        }
    }
}

// scatter edges into type-major order with fused gather index + inv_deg
__global__ void scatter_kernel(const int* __restrict__ src,
                               const int* __restrict__ dst,
                               const int* __restrict__ et) {
    __shared__ int soff[N_REL];
    int b = blockIdx.x;
    if (threadIdx.x < N_REL) soff[threadIdx.x] = g_blkoff[threadIdx.x * NPB + b];
    __syncthreads();
    #pragma unroll
    for (int i = 0; i < EPB / 256; i++) {
        int e = b * EPB + threadIdx.x + i * 256;
        if (e < N_EDGES) {
            int t = et[e];
            int pos = atomicAdd(&soff[t], 1);
            int d = dst[e];
            int c = g_cnt[d * N_REL + t];
            g_pgat[pos] = src[e] * N_REL + t;
            g_pdst[pos] = d;
            g_pinv[pos] = 1.0f / (float)(c > 1 ? c : 1);
        }
    }
}

__device__ __forceinline__ void bf16_split(float x, bf16& h, bf16& l) {
    h = __float2bfloat16(x);
    l = __float2bfloat16(x - __bfloat162float(h));
}

// split node embedding into bf16 hi/lo
__global__ void xsplit_kernel(const float* __restrict__ X,
                              bf16* __restrict__ hi, bf16* __restrict__ lo) {
    int i = blockIdx.x * 256 + threadIdx.x;
    bf16 h, l;
    bf16_split(X[i], h, l);
    hi[i] = h; lo[i] = l;
}

// transpose + split weights: Bhi/Blo[l][n][k] = split(W[l][rel][k][n] or root[l][k][n])
__global__ void wsplit_kernel(const float* __restrict__ W, const float* __restrict__ R,
                              bf16* __restrict__ Bhi, bf16* __restrict__ Blo) {
    __shared__ float t[32][33];
    int l  = blockIdx.z;
    int n0 = blockIdx.x * 32;
    int k0 = blockIdx.y * 32;
    int tx = threadIdx.x, ty = threadIdx.y;   // 32 x 8
    int rel = n0 >> 8;

    #pragma unroll
    for (int j = 0; j < 4; j++) {
        int k = k0 + ty + j * 8;
        float v;
        if (rel < 4)
            v = W[(((size_t)l * 4 + rel) * 256 + k) * 256 + (n0 & 255) + tx];
        else
            v = R[((size_t)l * 256 + k) * 256 + (n0 - 1024) + tx];
        t[ty + j * 8][tx] = v;
    }
    __syncthreads();
    #pragma unroll
    for (int j = 0; j < 4; j++) {
        int n = ty + j * 8;
        float x = t[tx][n];                    // = src[k0+tx][n0+n]
        bf16 h, lo;
        bf16_split(x, h, lo);
        size_t o = ((size_t)l * NCOL + n0 + n) * 256 + k0 + tx;
        Bhi[o] = h;
        Blo[o] = lo;
    }
}

// ---------------------------------------------------------------------------
// bf16 3-product GEMM via mma.sync: C[50000,1280] = X @ Wcat^T
//   C = Xhi*Bhi + Xlo*Bhi + Xhi*Blo  (fp32 accumulate)
// CTA tile 128x128, 8 warps (64x32 each), K chunks of 32 (hi|lo packed in
// one 128B SW128 row), 2-stage cp.async pipeline.
//   col tiles 0..7 -> g_H [N,1024];  col tiles 8..9 -> g_OUT (+bias)
// ---------------------------------------------------------------------------
#define STAGE_BYTES 32768          // A tile 16KB + B tile 16KB
#define SMEM_BYTES  (2 * STAGE_BYTES)

__device__ __forceinline__ void issue_stage(
    uint32_t smBase, int buf, int kc, int row0, int n0, int tid,
    const bf16* __restrict__ Xhi, const bf16* __restrict__ Xlo,
    const bf16* __restrict__ Bhi, const bf16* __restrict__ Blo)
{
    uint32_t aB = smBase + buf * STAGE_BYTES;
    uint32_t bB = aB + 16384;
    #pragma unroll
    for (int t = 0; t < 4; t++) {
        int j   = tid + t * 256;
        int row = j >> 3, ch = j & 7;
        int gr  = row0 + row;
        if (gr > N_NODES - 1) gr = N_NODES - 1;      // clamp; stores are guarded
        const bf16* src = (ch < 4 ? Xhi : Xlo) + (size_t)gr * 256 + kc * 32 + (ch & 3) * 8;
        CPA16(aB + SW(row * 128 + ch * 16), src);
    }
    #pragma unroll
    for (int t = 0; t < 4; t++) {
        int j   = tid + t * 256;
        int row = j >> 3, ch = j & 7;
        const bf16* src = (ch < 4 ? Bhi : Blo) + (size_t)(n0 + row) * 256 + kc * 32 + (ch & 3) * 8;
        CPA16(bB + SW(row * 128 + ch * 16), src);
    }
}

__global__ __launch_bounds__(256) void gemm_tc(
    const bf16* __restrict__ Xhi, const bf16* __restrict__ Xlo,
    const bf16* __restrict__ Bhi, const bf16* __restrict__ Blo,
    const float* __restrict__ bias,
    float* __restrict__ H, float* __restrict__ OUT)
{
    extern __shared__ __align__(1024) char sm[];
    const uint32_t smBase = smem_u32(sm);
    const int tid  = threadIdx.x;
    const int wid  = tid >> 5;
    const int lane = tid & 31;
    const int wm   = wid >> 2;          // 0..1  (64-row slab)
    const int wn   = wid & 3;           // 0..3  (32-col slab)
    const int n0   = blockIdx.x * 128;
    const int row0 = blockIdx.y * 128;

    float acc[4][4][4];
    #pragma unroll
    for (int i = 0; i < 4; i++)
        #pragma unroll
        for (int j = 0; j < 4; j++)
            #pragma unroll
            for (int k = 0; k < 4; k++) acc[i][j][k] = 0.f;

    const int lr  = lane & 7;
    const int ls1 = (lane >> 3) & 1;
    const int ls2 = lane >> 4;

    issue_stage(smBase, 0, 0, row0, n0, tid, Xhi, Xlo, Bhi, Blo);
    CPA_COMMIT();

    int buf = 0;
    for (int kc = 0; kc < 8; kc++) {
        if (kc < 7) {
            issue_stage(smBase, buf ^ 1, kc + 1, row0, n0, tid, Xhi, Xlo, Bhi, Blo);
            CPA_COMMIT();
            CPA_WAIT(1);
        } else {
            CPA_WAIT(0);
        }
        __syncthreads();

        uint32_t aB = smBase + buf * STAGE_BYTES;
        uint32_t bB = aB + 16384;

        #pragma unroll
        for (int kk = 0; kk < 2; kk++) {
            const int ch_hi = 2 * kk;        // 16B chunks 0..3 = hi, 4..7 = lo
            const int ch_lo = 4 + 2 * kk;

            uint32_t ahi[4][4], alo[4][4], bhi[2][4], blo[2][4];

            #pragma unroll
            for (int mf = 0; mf < 4; mf++) {
                int mrow = wm * 64 + mf * 16 + ls1 * 8 + lr;
                int ch   = ch_hi + ls2;
                ldsm_x4(ahi[mf][0], ahi[mf][1], ahi[mf][2], ahi[mf][3],
                        aB + SW(mrow * 128 + ch * 16));
            }
            #pragma unroll
            for (int np = 0; np < 2; np++) {
                int nrow = wn * 32 + np * 16 + ls2 * 8 + lr;
                int ch   = ch_hi + ls1;
                ldsm_x4(bhi[np][0], bhi[np][1], bhi[np][2], bhi[np][3],
                        bB + SW(nrow * 128 + ch * 16));
            }
            #pragma unroll
            for (int mf = 0; mf < 4; mf++)
                #pragma unroll
                for (int nf = 0; nf < 4; nf++)
                    MMA_BF16(acc[mf][nf], ahi[mf],
                             bhi[nf >> 1][(nf & 1) * 2], bhi[nf >> 1][(nf & 1) * 2 + 1]);

            #pragma unroll
            for (int mf = 0; mf < 4; mf++) {
                int mrow = wm * 64 + mf * 16 + ls1 * 8 + lr;
                int ch   = ch_lo + ls2;
                ldsm_x4(alo[mf][0], alo[mf][1], alo[mf][2], alo[mf][3],
                        aB + SW(mrow * 128 + ch * 16));
            }
            #pragma unroll
            for (int mf = 0; mf < 4; mf++)
                #pragma unroll
                for (int nf = 0; nf < 4; nf++)
                    MMA_BF16(acc[mf][nf], alo[mf],
                             bhi[nf >> 1][(nf & 1) * 2], bhi[nf >> 1][(nf & 1) * 2 + 1]);

            #pragma unroll
            for (int np = 0; np < 2; np++) {
                int nrow = wn * 32 + np * 16 + ls2 * 8 + lr;
                int ch   = ch_lo + ls1;
                ldsm_x4(blo[np][0], blo[np][1], blo[np][2], blo[np][3],
                        bB + SW(nrow * 128 + ch * 16));
            }
            #pragma unroll
            for (int mf = 0; mf < 4; mf++)
                #pragma unroll
                for (int nf = 0; nf < 4; nf++)
                    MMA_BF16(acc[mf][nf], ahi[mf],
                             blo[nf >> 1][(nf & 1) * 2], blo[nf >> 1][(nf & 1) * 2 + 1]);
        }
        __syncthreads();
        buf ^= 1;
    }

    // ---- epilogue: direct fp32 stores ----
    const int g  = lane >> 2;
    const int tg = lane & 3;
    const bool isroot = (n0 >= 1024);

    #pragma unroll
    for (int nf = 0; nf < 4; nf++) {
        int col = n0 + wn * 32 + nf * 8 + tg * 2;
        float b0 = 0.f, b1 = 0.f;
        if (isroot) { b0 = bias[col - 1024]; b1 = bias[col - 1023]; }
        #pragma unroll
        for (int mf = 0; mf < 4; mf++) {
            int r0 = row0 + wm * 64 + mf * 16 + g;
            int r1 = r0 + 8;
            float2 v0 = make_float2(acc[mf][nf][0] + b0, acc[mf][nf][1] + b1);
            float2 v1 = make_float2(acc[mf][nf][2] + b0, acc[mf][nf][3] + b1);
            if (isroot) {
                if (r0 < N_NODES) *(float2*)(OUT + (size_t)r0 * 256 + col - 1024) = v0;
                if (r1 < N_NODES) *(float2*)(OUT + (size_t)r1 * 256 + col - 1024) = v1;
            } else {
                if (r0 < N_NODES) *(float2*)(H + (size_t)r0 * 1024 + col) = v0;
                if (r1 < N_NODES) *(float2*)(H + (size_t)r1 * 1024 + col) = v1;
            }
        }
    }
}

// ---------------------------------------------------------------------------
// Edge aggregation (type-major partitioned): OUT[dst] += inv * H[gat]
// Gather source per type is 51MB -> L2 resident.
// ---------------------------------------------------------------------------
__global__ void edge_kernel(const float* __restrict__ H,
                            float* __restrict__ OUT)
{
    int e    = blockIdx.x * 4 + (threadIdx.x >> 6);
    int lane = threadIdx.x & 63;

    int   g   = g_pgat[e];
    int   d   = g_pdst[e];
    float inv = g_pinv[e];

    float4 v = *(const float4*)(H + (size_t)g * DIM + lane * 4);
    v.x *= inv; v.y *= inv; v.z *= inv; v.w *= inv;

    float* p = OUT + (size_t)d * DIM + lane * 4;
    asm volatile("red.global.add.v4.f32 [%0], {%1, %2, %3, %4};"
                 :: "l"(p), "f"(v.x), "f"(v.y), "f"(v.z), "f"(v.w)
                 : "memory");
}

// ---------------------------------------------------------------------------
// LayerNorm + ELU + residual (warp per row, 8 floats/lane), fused bf16 split
// ---------------------------------------------------------------------------
__global__ __launch_bounds__(256) void ln_kernel(
        const float* __restrict__ OUT,
        const float* __restrict__ Xin,
        const float* __restrict__ gamma,
        const float* __restrict__ beta,
        float* __restrict__ Xout,
        bf16* __restrict__ Xhi,
        bf16* __restrict__ Xlo)
{
    int row  = blockIdx.x * 8 + (threadIdx.x >> 5);
    int lane = threadIdx.x & 31;
    size_t base = (size_t)row * DIM + lane * 8;

    float v[8];
    *(float4*)&v[0] = *(const float4*)(OUT + base);
    *(float4*)&v[4] = *(const float4*)(OUT + base + 4);

    float s = v[0] + v[1] + v[2] + v[3] + v[4] + v[5] + v[6] + v[7];
    #pragma unroll
    for (int o = 16; o > 0; o >>= 1) s += __shfl_xor_sync(0xffffffffu, s, o);
    float mu = s * (1.0f / DIM);

    float q = 0.f;
    #pragma unroll
    for (int k = 0; k < 8; k++) { float dl = v[k] - mu; q += dl * dl; }
    #pragma unroll
    for (int o = 16; o > 0; o >>= 1) q += __shfl_xor_sync(0xffffffffu, q, o);
    float rstd = rsqrtf(q * (1.0f / DIM) + LN_EPS);

    float gmv[8], btv[8], xi[8];
    *(float4*)&gmv[0] = *(const float4*)(gamma + lane * 8);
    *(float4*)&gmv[4] = *(const float4*)(gamma + lane * 8 + 4);
    *(float4*)&btv[0] = *(const float4*)(beta + lane * 8);
    *(float4*)&btv[4] = *(const float4*)(beta + lane * 8 + 4);
    *(float4*)&xi[0]  = *(const float4*)(Xin + base);
    *(float4*)&xi[4]  = *(const float4*)(Xin + base + 4);

    float r[8];
    ushort hi[8], lo[8];
    #pragma unroll
    for (int k = 0; k < 8; k++) {
        float y = (v[k] - mu) * rstd * gmv[k] + btv[k];
        y = (y > 0.f) ? y : expm1f(y);
        r[k] = y + xi[k];
        bf16 h, l;
        bf16_split(r[k], h, l);
        hi[k] = __bfloat16_as_ushort(h);
        lo[k] = __bfloat16_as_ushort(l);
    }

    *(float4*)(Xout + base)     = *(float4*)&r[0];
    *(float4*)(Xout + base + 4) = *(float4*)&r[4];
    *(uint4*)(Xhi + base) = *(uint4*)&hi[0];
    *(uint4*)(Xlo + base) = *(uint4*)&lo[0];
}

// ---------------------------------------------------------------------------
// Driver
// ---------------------------------------------------------------------------
extern "C" void kernel_launch(void* const* d_in, const int* in_sizes, int n_in,
                              void* d_out, int out_size)
{
    const float* node    = (const float*)d_in[0];
    const float* weights = (const float*)d_in[1];   // [4,4,256,256]
    const float* roots   = (const float*)d_in[2];   // [4,256,256]
    const float* biases  = (const float*)d_in[3];   // [4,256]
    const float* gamma   = (const float*)d_in[4];   // [4,256]
    const float* beta    = (const float*)d_in[5];   // [4,256]
    const int*   eidx    = (const int*)d_in[6];     // [2,800000]
    const int*   etype   = (const int*)d_in[7];     // [800000]
    const int*   srcv    = eidx;
    const int*   dstv    = eidx + N_EDGES;
    float*       out     = (float*)d_out;

    float *H, *OUTb, *bufA, *bufB;
    bf16 *Xhi, *Xlo, *Bhi, *Blo;
    cudaGetSymbolAddress((void**)&H,    g_H);
    cudaGetSymbolAddress((void**)&OUTb, g_OUT);
    cudaGetSymbolAddress((void**)&bufA, g_bufA);
    cudaGetSymbolAddress((void**)&bufB, g_bufB);
    cudaGetSymbolAddress((void**)&Xhi,  g_Xhi);
    cudaGetSymbolAddress((void**)&Xlo,  g_Xlo);
    cudaGetSymbolAddress((void**)&Bhi,  g_Bhi);
    cudaGetSymbolAddress((void**)&Blo,  g_Blo);

    static int smem_set = 0;
    if (!smem_set) {
        cudaFuncSetAttribute(gemm_tc, cudaFuncAttributeMaxDynamicSharedMemorySize, SMEM_BYTES);
        smem_set = 1;
    }

    // once per launch: degree histogram, edge partition, operand splits
    zero_cnt_kernel<<<(N_NODES * N_REL + 255) / 256, 256>>>();
    count_kernel<<<(N_EDGES + 255) / 256, 256>>>(dstv, etype);
    hist_kernel<<<NPB, 256>>>(etype);
    scan_kernel<<<1, 32>>>();
    scatter_kernel<<<NPB, 256>>>(srcv, dstv, etype);
    wsplit_kernel<<<dim3(NCOL / 32, DIM / 32, DEPTH), dim3(32, 8)>>>(weights, roots, Bhi, Blo);
    xsplit_kernel<<<N_NODES * DIM / 256, 256>>>(node, Xhi, Xlo);

    for (int l = 0; l < DEPTH; l++) {
        const float* Xin  = (l == 0) ? node : ((l & 1) ? bufA : bufB);
        float*       Xout = (l == 3) ? out  : ((l & 1) ? bufB : bufA);

        gemm_tc<<<dim3(10, 391), 256, SMEM_BYTES>>>(
            Xhi, Xlo,
            Bhi + (size_t)l * NCOL * DIM,
            Blo + (size_t)l * NCOL * DIM,
            biases + l * DIM,
            H, OUTb);

        edge_kernel<<<N_EDGES / 4, 256>>>(H, OUTb);

        ln_kernel<<<N_NODES / 8, 256>>>(OUTb, Xin, gamma + l * DIM, beta + l * DIM,
                                        Xout, Xhi, Xlo);
    }
}